// round 4
// baseline (speedup 1.0000x reference)
#include <cuda_runtime.h>

#define BS    2048
#define NINP  512
#define NHID  512
#define KBLK  16
#define TT    8
#define MM    32
#define NTOT  (BS*KBLK)        // 32768
#define GI_COLS (TT*3*MM)      // 768
#define TPB   448              // 14 warps; grid 147 ~= #SMs

// scratch for gi = x @ W_ih^T + b_ih, per-b (k-independent)
__device__ float g_gi[BS * GI_COLS];   // [2048][768], 6 MB

// ---------------------------------------------------------------------------
// Kernel 1: gi[b][t*96+g] = sum_k x[b][k]*W_ih[t][g][k] + b_ih[t][g]
// ---------------------------------------------------------------------------
__global__ void __launch_bounds__(256) gemm_gi_kernel(
    const float* __restrict__ A,
    const float* __restrict__ B,
    const float* __restrict__ bias)
{
    __shared__ float As[32][65];
    __shared__ float Bs[32][65];

    const int tid = threadIdx.x;
    const int tx  = tid & 15;
    const int ty  = tid >> 4;
    const int m0  = blockIdx.y * 64;
    const int n0  = blockIdx.x * 64;
    const int lr  = tid >> 3;
    const int lk  = (tid & 7) * 4;

    float acc[4][4];
#pragma unroll
    for (int i = 0; i < 4; i++)
#pragma unroll
        for (int j = 0; j < 4; j++) acc[i][j] = 0.f;

    for (int k0 = 0; k0 < NINP; k0 += 32) {
#pragma unroll
        for (int r = 0; r < 2; r++) {
            float4 va = *(const float4*)&A[(m0 + lr + r * 32) * NINP + k0 + lk];
            As[lk + 0][lr + r * 32] = va.x;
            As[lk + 1][lr + r * 32] = va.y;
            As[lk + 2][lr + r * 32] = va.z;
            As[lk + 3][lr + r * 32] = va.w;
            float4 vb = *(const float4*)&B[(n0 + lr + r * 32) * NINP + k0 + lk];
            Bs[lk + 0][lr + r * 32] = vb.x;
            Bs[lk + 1][lr + r * 32] = vb.y;
            Bs[lk + 2][lr + r * 32] = vb.z;
            Bs[lk + 3][lr + r * 32] = vb.w;
        }
        __syncthreads();
#pragma unroll
        for (int k = 0; k < 32; k++) {
            float a[4], b[4];
#pragma unroll
            for (int i = 0; i < 4; i++) a[i] = As[k][ty + i * 16];
#pragma unroll
            for (int j = 0; j < 4; j++) b[j] = Bs[k][tx + j * 16];
#pragma unroll
            for (int i = 0; i < 4; i++)
#pragma unroll
                for (int j = 0; j < 4; j++)
                    acc[i][j] = fmaf(a[i], b[j], acc[i][j]);
        }
        __syncthreads();
    }

#pragma unroll
    for (int j = 0; j < 4; j++) {
        float bj = bias[n0 + tx + j * 16];
#pragma unroll
        for (int i = 0; i < 4; i++)
            g_gi[(m0 + ty + i * 16) * GI_COLS + n0 + tx + j * 16] = acc[i][j] + bj;
    }
}

// ---------------------------------------------------------------------------
// Kernel 2: pair-of-threads-per-n. Online argmax pass (no hnext storage),
// then recompute hnext for the single selected template. No spills.
// ---------------------------------------------------------------------------
#define SMEM_FLOATS (TT*96*MM + TT*MM*16 + MM*16 + TT*96)   // 29952
#define SMEM_BYTES  (SMEM_FLOATS * 4)                        // 119808

__global__ void __launch_bounds__(TPB, 1) fused4_kernel(
    const float* __restrict__ h,
    const float* __restrict__ W_hh,
    const float* __restrict__ b_hh,
    const float* __restrict__ w_read,
    const float* __restrict__ w_write,
    const float* __restrict__ gum,
    float* __restrict__ out)
{
    extern __shared__ float sm[];
    float* Wg  = sm;               // W_hh natural layout [t][g][m]: 24576
    float* Wwr = Wg + TT*96*MM;    // w_write [t][l][f]:             4096
    float* Wrd = Wwr + TT*MM*16;   // w_read [m][f]:                  512
    float* bh  = Wrd + MM*16;      // b_hh [t][g]:                    768
    const int tid = threadIdx.x;

    {   // stage weights (contiguous float4 copies)
        float4* d = (float4*)Wg; const float4* s = (const float4*)W_hh;
        for (int i = tid; i < TT*96*MM/4; i += TPB) d[i] = s[i];
        d = (float4*)Wwr; s = (const float4*)w_write;
        for (int i = tid; i < TT*MM*16/4; i += TPB) d[i] = s[i];
        d = (float4*)Wrd; s = (const float4*)w_read;
        for (int i = tid; i < MM*16/4; i += TPB) d[i] = s[i];
        d = (float4*)bh; s = (const float4*)b_hh;
        for (int i = tid; i < TT*96/4; i += TPB) d[i] = s[i];
    }
    __syncthreads();

    const int gtid = blockIdx.x * TPB + tid;
    if (gtid >= 2 * NTOT) return;           // whole trailing warps exit
    const int n    = gtid >> 1;
    const int half = gtid & 1;
    const int l0   = half * 16;
    const int b    = n >> 4;

    float h2[32];
    {
        const float4* hp = (const float4*)(h + n * MM);
#pragma unroll
        for (int i = 0; i < 8; i++) {
            float4 v = hp[i];
            h2[4*i] = v.x; h2[4*i+1] = v.y; h2[4*i+2] = v.z; h2[4*i+3] = v.w;
        }
    }

    // h_read[f] = sum_m h2[m] * w_read[m][f]  (computed in both pair threads)
    float hr[16];
#pragma unroll
    for (int f = 0; f < 16; f++) hr[f] = 0.f;
#pragma unroll
    for (int m = 0; m < 32; m++) {
        const float4* w = (const float4*)(Wrd + m * 16);
        float hm = h2[m];
#pragma unroll
        for (int f4 = 0; f4 < 4; f4++) {
            float4 v = w[f4];
            hr[4*f4]   = fmaf(hm, v.x, hr[4*f4]);
            hr[4*f4+1] = fmaf(hm, v.y, hr[4*f4+1]);
            hr[4*f4+2] = fmaf(hm, v.z, hr[4*f4+2]);
            hr[4*f4+3] = fmaf(hm, v.w, hr[4*f4+3]);
        }
    }

    // gumbel noise prefetch
    float g8[8];
    {
        const float4* gp = (const float4*)(gum + n * TT);
        float4 a = gp[0], c = gp[1];
        g8[0]=a.x; g8[1]=a.y; g8[2]=a.z; g8[3]=a.w;
        g8[4]=c.x; g8[5]=c.y; g8[6]=c.z; g8[7]=c.w;
    }

    float rmax = -1e30f, rsum = 0.f;
    int amax = 0;

    // ---- pass 1: online softmax / argmax over templates ----
#pragma unroll 1
    for (int t = 0; t < TT; t++) {
        const float* gib = g_gi + b * GI_COLS + t * 96;
        const float* wt  = Wg  + t * 96 * MM;
        const float* wwt = Wwr + t * MM * 16;
        const float* bht = bh  + t * 96;
        float lgp = 0.f;

#pragma unroll 2
        for (int l4 = 0; l4 < 4; l4++) {
            float Ga[4], Gb[4], Gc[4];
            *(float4*)Ga = *(const float4*)(gib + l0 + 4*l4);
            *(float4*)Gb = *(const float4*)(gib + 32 + l0 + 4*l4);
            *(float4*)Gc = *(const float4*)(gib + 64 + l0 + 4*l4);
#pragma unroll
            for (int li = 0; li < 4; li++) {
                const int l = l0 + 4*l4 + li;
                float ar = bht[l], az = bht[32 + l], an = bht[64 + l];
                const float4* wr = (const float4*)(wt + l * 32);
                const float4* wz = (const float4*)(wt + (32 + l) * 32);
                const float4* wn = (const float4*)(wt + (64 + l) * 32);
#pragma unroll
                for (int m4 = 0; m4 < 8; m4++) {
                    float4 a = wr[m4], bb = wz[m4], c = wn[m4];
                    ar = fmaf(a.x,  h2[4*m4],   ar);
                    ar = fmaf(a.y,  h2[4*m4+1], ar);
                    ar = fmaf(a.z,  h2[4*m4+2], ar);
                    ar = fmaf(a.w,  h2[4*m4+3], ar);
                    az = fmaf(bb.x, h2[4*m4],   az);
                    az = fmaf(bb.y, h2[4*m4+1], az);
                    az = fmaf(bb.z, h2[4*m4+2], az);
                    az = fmaf(bb.w, h2[4*m4+3], az);
                    an = fmaf(c.x,  h2[4*m4],   an);
                    an = fmaf(c.y,  h2[4*m4+1], an);
                    an = fmaf(c.z,  h2[4*m4+2], an);
                    an = fmaf(c.w,  h2[4*m4+3], an);
                }
                // av = w_write[t][l] . h_read   (16-wide dot)
                const float4* ww = (const float4*)(wwt + l * 16);
                float4 w0 = ww[0], w1 = ww[1], w2 = ww[2], w3 = ww[3];
                float av;
                av = w0.x * hr[0];
                av = fmaf(w0.y, hr[1],  av);
                av = fmaf(w0.z, hr[2],  av);
                av = fmaf(w0.w, hr[3],  av);
                av = fmaf(w1.x, hr[4],  av);
                av = fmaf(w1.y, hr[5],  av);
                av = fmaf(w1.z, hr[6],  av);
                av = fmaf(w1.w, hr[7],  av);
                av = fmaf(w2.x, hr[8],  av);
                av = fmaf(w2.y, hr[9],  av);
                av = fmaf(w2.z, hr[10], av);
                av = fmaf(w2.w, hr[11], av);
                av = fmaf(w3.x, hr[12], av);
                av = fmaf(w3.y, hr[13], av);
                av = fmaf(w3.z, hr[14], av);
                av = fmaf(w3.w, hr[15], av);

                float r  = __fdividef(1.f, 1.f + __expf(-(Ga[li] + ar)));
                float z  = __fdividef(1.f, 1.f + __expf(-(Gb[li] + az)));
                float xn = Gc[li] + r * an;
                float e2 = __expf(-2.f * xn);
                float nn = __fdividef(1.f - e2, 1.f + e2);   // tanh
                float hn = (1.f - z) * nn + z * h2[l];
                lgp = fmaf(hn, av, lgp);
            }
        }
        // combine pair halves: one shuffle (commutative add -> identical both)
        float lg = lgp + __shfl_xor_sync(0xffffffffu, lgp, 1);
        float s  = (lg + g8[t]) * 2.0f;     // /TAU, TAU=0.5
        if (s > rmax) {
            rsum = rsum * __expf(rmax - s) + 1.f;
            rmax = s; amax = t;
        } else {
            rsum += __expf(s - rmax);
        }
    }

    float p = __fdividef(1.f, rsum);        // softmax value at argmax
    float attv = (1.f + p) - p;             // straight-through residual, exact

    // ---- pass 2: recompute hnext for the selected template only ----
    {
        const float* gib = g_gi + b * GI_COLS + amax * 96;
        const float* wt  = Wg  + amax * 96 * MM;
        const float* bht = bh  + amax * 96;
        float4* ho = (float4*)(out + n * MM + l0);

#pragma unroll 2
        for (int l4 = 0; l4 < 4; l4++) {
            float Ga[4], Gb[4], Gc[4];
            *(float4*)Ga = *(const float4*)(gib + l0 + 4*l4);
            *(float4*)Gb = *(const float4*)(gib + 32 + l0 + 4*l4);
            *(float4*)Gc = *(const float4*)(gib + 64 + l0 + 4*l4);
            float o4[4];
#pragma unroll
            for (int li = 0; li < 4; li++) {
                const int l = l0 + 4*l4 + li;
                float ar = bht[l], az = bht[32 + l], an = bht[64 + l];
                const float4* wr = (const float4*)(wt + l * 32);
                const float4* wz = (const float4*)(wt + (32 + l) * 32);
                const float4* wn = (const float4*)(wt + (64 + l) * 32);
#pragma unroll
                for (int m4 = 0; m4 < 8; m4++) {
                    float4 a = wr[m4], bb = wz[m4], c = wn[m4];
                    ar = fmaf(a.x,  h2[4*m4],   ar);
                    ar = fmaf(a.y,  h2[4*m4+1], ar);
                    ar = fmaf(a.z,  h2[4*m4+2], ar);
                    ar = fmaf(a.w,  h2[4*m4+3], ar);
                    az = fmaf(bb.x, h2[4*m4],   az);
                    az = fmaf(bb.y, h2[4*m4+1], az);
                    az = fmaf(bb.z, h2[4*m4+2], az);
                    az = fmaf(bb.w, h2[4*m4+3], az);
                    an = fmaf(c.x,  h2[4*m4],   an);
                    an = fmaf(c.y,  h2[4*m4+1], an);
                    an = fmaf(c.z,  h2[4*m4+2], an);
                    an = fmaf(c.w,  h2[4*m4+3], an);
                }
                float r  = __fdividef(1.f, 1.f + __expf(-(Ga[li] + ar)));
                float z  = __fdividef(1.f, 1.f + __expf(-(Gb[li] + az)));
                float xn = Gc[li] + r * an;
                float e2 = __expf(-2.f * xn);
                float nn = __fdividef(1.f - e2, 1.f + e2);   // tanh
                float hn = (1.f - z) * nn + z * h2[l];
                o4[li] = attv * hn;
            }
            ho[l4] = *(float4*)o4;
        }
    }

    if (half == 0) {
        float* ao = out + BS * NHID + n * TT;
#pragma unroll
        for (int t = 0; t < TT; t++) ao[t] = (t == amax) ? attv : 0.f;
    }
}

// ---------------------------------------------------------------------------
extern "C" void kernel_launch(void* const* d_in, const int* in_sizes, int n_in,
                              void* d_out, int out_size)
{
    const float* x       = (const float*)d_in[0];
    const float* h       = (const float*)d_in[1];
    const float* W_ih    = (const float*)d_in[2];
    const float* W_hh    = (const float*)d_in[3];
    const float* b_ih    = (const float*)d_in[4];
    const float* b_hh    = (const float*)d_in[5];
    const float* w_read  = (const float*)d_in[6];
    const float* w_write = (const float*)d_in[7];
    const float* gum     = (const float*)d_in[8];
    float* out = (float*)d_out;

    dim3 g1(GI_COLS / 64, BS / 64);           // (12, 32)
    gemm_gi_kernel<<<g1, 256>>>(x, W_ih, b_ih);

    cudaFuncSetAttribute(fused4_kernel,
                         cudaFuncAttributeMaxDynamicSharedMemorySize, SMEM_BYTES);
    fused4_kernel<<<(2 * NTOT + TPB - 1) / TPB, TPB, SMEM_BYTES>>>(
        h, W_hh, b_hh, w_read, w_write, gum, out);
}

// round 5
// speedup vs baseline: 1.6768x; 1.6768x over previous
#include <cuda_runtime.h>

#define BS    2048
#define NINP  512
#define NHID  512
#define KBLK  16
#define TT    8
#define MM    32
#define NTOT  (BS*KBLK)        // 32768
#define GI_COLS (TT*3*MM)      // 768

typedef unsigned long long u64;

// device scratch
__device__ float g_gi[BS * GI_COLS];       // [2048][768], 6 MB
__device__ float g_hn[TT * NTOT * MM];     // hnext [t][n][m], 32 MB
__device__ float g_lg[NTOT * TT];          // logits [n][t], 1 MB

// ---- packed f32x2 helpers (Blackwell FFMA2) --------------------------------
__device__ __forceinline__ void fma2(u64& acc, u64 a, u64 b) {
    asm("fma.rn.f32x2 %0, %1, %2, %0;" : "+l"(acc) : "l"(a), "l"(b));
}
__device__ __forceinline__ u64 pk(float lo, float hi) {
    u64 r; asm("mov.b64 %0, {%1, %2};" : "=l"(r) : "f"(lo), "f"(hi)); return r;
}
__device__ __forceinline__ void unpk(float& lo, float& hi, u64 v) {
    asm("mov.b64 {%0, %1}, %2;" : "=f"(lo), "=f"(hi) : "l"(v));
}
__device__ __forceinline__ float hadd(u64 v) {
    float a, b; unpk(a, b, v); return a + b;
}

// ---------------------------------------------------------------------------
// Kernel 1: gi[b][t*96+g] = sum_k x[b][k]*W_ih[t][g][k] + b_ih[t][g]
// ---------------------------------------------------------------------------
__global__ void __launch_bounds__(256) gemm_gi_kernel(
    const float* __restrict__ A,
    const float* __restrict__ B,
    const float* __restrict__ bias)
{
    __shared__ float As[32][65];
    __shared__ float Bs[32][65];

    const int tid = threadIdx.x;
    const int tx  = tid & 15;
    const int ty  = tid >> 4;
    const int m0  = blockIdx.y * 64;
    const int n0  = blockIdx.x * 64;
    const int lr  = tid >> 3;
    const int lk  = (tid & 7) * 4;

    float acc[4][4];
#pragma unroll
    for (int i = 0; i < 4; i++)
#pragma unroll
        for (int j = 0; j < 4; j++) acc[i][j] = 0.f;

    for (int k0 = 0; k0 < NINP; k0 += 32) {
#pragma unroll
        for (int r = 0; r < 2; r++) {
            float4 va = *(const float4*)&A[(m0 + lr + r * 32) * NINP + k0 + lk];
            As[lk + 0][lr + r * 32] = va.x;
            As[lk + 1][lr + r * 32] = va.y;
            As[lk + 2][lr + r * 32] = va.z;
            As[lk + 3][lr + r * 32] = va.w;
            float4 vb = *(const float4*)&B[(n0 + lr + r * 32) * NINP + k0 + lk];
            Bs[lk + 0][lr + r * 32] = vb.x;
            Bs[lk + 1][lr + r * 32] = vb.y;
            Bs[lk + 2][lr + r * 32] = vb.z;
            Bs[lk + 3][lr + r * 32] = vb.w;
        }
        __syncthreads();
#pragma unroll
        for (int k = 0; k < 32; k++) {
            float a[4], b[4];
#pragma unroll
            for (int i = 0; i < 4; i++) a[i] = As[k][ty + i * 16];
#pragma unroll
            for (int j = 0; j < 4; j++) b[j] = Bs[k][tx + j * 16];
#pragma unroll
            for (int i = 0; i < 4; i++)
#pragma unroll
                for (int j = 0; j < 4; j++)
                    acc[i][j] = fmaf(a[i], b[j], acc[i][j]);
        }
        __syncthreads();
    }

#pragma unroll
    for (int j = 0; j < 4; j++) {
        float bj = bias[n0 + tx + j * 16];
#pragma unroll
        for (int i = 0; i < 4; i++)
            g_gi[(m0 + ty + i * 16) * GI_COLS + n0 + tx + j * 16] = acc[i][j] + bj;
    }
}

// ---------------------------------------------------------------------------
// Kernel A: per-(n, t) gates + hnext + logit.  blockIdx.y = template t.
// Packed f32x2 FMA for the m-reduction.  16 warps/SM (2 blocks x 256 thr).
// ---------------------------------------------------------------------------
__global__ void __launch_bounds__(256, 2) gates_kernel(
    const float* __restrict__ h,
    const float* __restrict__ W_hh,
    const float* __restrict__ b_hh,
    const float* __restrict__ w_read,
    const float* __restrict__ w_write)
{
    __shared__ float Wg[96 * 32];    // gate weights, this template     12 KB
    __shared__ float Ww[32 * 16];    // w_write[t]                       2 KB
    __shared__ float Wr[32 * 16];    // w_read                           2 KB
    __shared__ float bs[96];         // b_hh[t]

    const int tid = threadIdx.x;
    const int t   = blockIdx.y;

    {   // stage this template's weights
        const float4* s1 = (const float4*)(W_hh + t * 96 * 32);
        float4* d1 = (float4*)Wg;
        for (int i = tid; i < 96 * 32 / 4; i += 256) d1[i] = s1[i];
        const float4* s2 = (const float4*)(w_write + t * 32 * 16);
        float4* d2 = (float4*)Ww;
        if (tid < 128) d2[tid] = s2[tid];
        const float4* s3 = (const float4*)w_read;
        float4* d3 = (float4*)Wr;
        if (tid >= 128 && tid < 256) d3[tid - 128] = s3[tid - 128];
        const float4* s4 = (const float4*)(b_hh + t * 96);
        float4* d4 = (float4*)bs;
        if (tid < 24) d4[tid] = s4[tid];
    }
    __syncthreads();

    const int n = blockIdx.x * 256 + tid;
    const int b = n >> 4;

    // load h2 (scalar for hr/pointwise, packed for gate reductions)
    float h2s[32];
    {
        const float4* hp = (const float4*)(h + n * MM);
#pragma unroll
        for (int i = 0; i < 8; i++) {
            float4 v = hp[i];
            h2s[4*i] = v.x; h2s[4*i+1] = v.y; h2s[4*i+2] = v.z; h2s[4*i+3] = v.w;
        }
    }

    // h_read[f] = sum_m h2[m]*w_read[m][f], then pack into 8 f32x2 pairs
    u64 hrp[8];
    {
        float hr[16];
#pragma unroll
        for (int f = 0; f < 16; f++) hr[f] = 0.f;
#pragma unroll
        for (int m = 0; m < 32; m++) {
            const float4* w = (const float4*)(Wr + m * 16);
            float hm = h2s[m];
#pragma unroll
            for (int f4 = 0; f4 < 4; f4++) {
                float4 v = w[f4];
                hr[4*f4]   = fmaf(hm, v.x, hr[4*f4]);
                hr[4*f4+1] = fmaf(hm, v.y, hr[4*f4+1]);
                hr[4*f4+2] = fmaf(hm, v.z, hr[4*f4+2]);
                hr[4*f4+3] = fmaf(hm, v.w, hr[4*f4+3]);
            }
        }
#pragma unroll
        for (int f2 = 0; f2 < 8; f2++) hrp[f2] = pk(hr[2*f2], hr[2*f2+1]);
    }

    // pack h2
    u64 h2p[16];
#pragma unroll
    for (int i = 0; i < 16; i++) h2p[i] = pk(h2s[2*i], h2s[2*i+1]);

    const float* gib = g_gi + b * GI_COLS + t * 96;
    float* hout = g_hn + (t * NTOT + n) * MM;
    float lgp = 0.f;

#pragma unroll 2
    for (int l4 = 0; l4 < 8; l4++) {
        float Ga[4], Gb[4], Gc[4];
        *(float4*)Ga = *(const float4*)(gib + 4*l4);
        *(float4*)Gb = *(const float4*)(gib + 32 + 4*l4);
        *(float4*)Gc = *(const float4*)(gib + 64 + 4*l4);
        float hn4[4];
#pragma unroll
        for (int li = 0; li < 4; li++) {
            const int l = 4*l4 + li;
            const ulonglong2* wr = (const ulonglong2*)(Wg + l * 32);
            const ulonglong2* wz = (const ulonglong2*)(Wg + (32 + l) * 32);
            const ulonglong2* wn = (const ulonglong2*)(Wg + (64 + l) * 32);
            u64 accr = pk(bs[l],      0.f);
            u64 accz = pk(bs[32 + l], 0.f);
            u64 accn = pk(bs[64 + l], 0.f);
#pragma unroll
            for (int q = 0; q < 8; q++) {
                ulonglong2 wa = wr[q];
                fma2(accr, wa.x, h2p[2*q]); fma2(accr, wa.y, h2p[2*q+1]);
                ulonglong2 wb = wz[q];
                fma2(accz, wb.x, h2p[2*q]); fma2(accz, wb.y, h2p[2*q+1]);
                ulonglong2 wc = wn[q];
                fma2(accn, wc.x, h2p[2*q]); fma2(accn, wc.y, h2p[2*q+1]);
            }
            float ar = hadd(accr), az = hadd(accz), an = hadd(accn);

            // av = w_write[t][l] . h_read  (packed)
            const ulonglong2* ww = (const ulonglong2*)(Ww + l * 16);
            u64 acca = pk(0.f, 0.f);
#pragma unroll
            for (int q = 0; q < 4; q++) {
                ulonglong2 w = ww[q];
                fma2(acca, w.x, hrp[2*q]); fma2(acca, w.y, hrp[2*q+1]);
            }
            float av = hadd(acca);

            float r  = __fdividef(1.f, 1.f + __expf(-(Ga[li] + ar)));
            float z  = __fdividef(1.f, 1.f + __expf(-(Gb[li] + az)));
            float xn = Gc[li] + r * an;
            float e2 = __expf(-2.f * xn);
            float nn = __fdividef(1.f - e2, 1.f + e2);       // tanh
            float hn = (1.f - z) * nn + z * h2s[l];
            hn4[li] = hn;
            lgp = fmaf(hn, av, lgp);
        }
        *(float4*)(hout + 4*l4) = *(float4*)hn4;
    }

    g_lg[n * TT + t] = lgp;
}

// ---------------------------------------------------------------------------
// Kernel B: gumbel softmax + hard select + gather + outputs
// ---------------------------------------------------------------------------
__global__ void __launch_bounds__(256) select_kernel(
    const float* __restrict__ gum,
    float* __restrict__ out)
{
    const int n = blockIdx.x * 256 + threadIdx.x;

    float s[8];
    {
        const float4* lp = (const float4*)(g_lg + n * TT);
        const float4* gp = (const float4*)(gum + n * TT);
        float4 l0 = lp[0], l1 = lp[1], g0 = gp[0], g1 = gp[1];
        s[0] = (l0.x + g0.x) * 2.f; s[1] = (l0.y + g0.y) * 2.f;
        s[2] = (l0.z + g0.z) * 2.f; s[3] = (l0.w + g0.w) * 2.f;
        s[4] = (l1.x + g1.x) * 2.f; s[5] = (l1.y + g1.y) * 2.f;
        s[6] = (l1.z + g1.z) * 2.f; s[7] = (l1.w + g1.w) * 2.f;
    }
    float smax = s[0];
    int amax = 0;
#pragma unroll
    for (int t = 1; t < 8; t++)
        if (s[t] > smax) { smax = s[t]; amax = t; }
    float sum = 0.f;
#pragma unroll
    for (int t = 0; t < 8; t++) sum += __expf(s[t] - smax);

    float p = __fdividef(1.f, sum);         // softmax at argmax
    float attv = (1.f + p) - p;             // straight-through residual, exact

    const float4* hp = (const float4*)(g_hn + (amax * NTOT + n) * MM);
    float4* ho = (float4*)(out + n * MM);
#pragma unroll
    for (int i = 0; i < 8; i++) {
        float4 v = hp[i];
        v.x *= attv; v.y *= attv; v.z *= attv; v.w *= attv;
        ho[i] = v;
    }
    float* ao = out + BS * NHID + n * TT;
#pragma unroll
    for (int t = 0; t < 8; t++) ao[t] = (t == amax) ? attv : 0.f;
}

// ---------------------------------------------------------------------------
extern "C" void kernel_launch(void* const* d_in, const int* in_sizes, int n_in,
                              void* d_out, int out_size)
{
    const float* x       = (const float*)d_in[0];
    const float* h       = (const float*)d_in[1];
    const float* W_ih    = (const float*)d_in[2];
    const float* W_hh    = (const float*)d_in[3];
    const float* b_ih    = (const float*)d_in[4];
    const float* b_hh    = (const float*)d_in[5];
    const float* w_read  = (const float*)d_in[6];
    const float* w_write = (const float*)d_in[7];
    const float* gum     = (const float*)d_in[8];
    float* out = (float*)d_out;

    dim3 g1(GI_COLS / 64, BS / 64);           // (12, 32)
    gemm_gi_kernel<<<g1, 256>>>(x, W_ih, b_ih);

    dim3 g2(NTOT / 256, TT);                  // (128, 8)
    gates_kernel<<<g2, 256>>>(h, W_hh, b_hh, w_read, w_write);

    select_kernel<<<NTOT / 256, 256>>>(gum, out);
}